// round 15
// baseline (speedup 1.0000x reference)
#include <cuda_runtime.h>
#include <cuda_bf16.h>
#include <cuda_fp16.h>
#include <cstdint>

#define BATCH 256
#define INF   1024
#define OUTF  128
#define KD    8
#define NCOLS (OUTF * KD)     // 1024
#define OUTW  (INF + OUTF)    // 1152

// Device scratch (no allocs allowed)
__device__ __align__(16) __half g_Mh[BATCH * NCOLS];   // Mh = (x @ T) * log2(e), fp16

__device__ __forceinline__ uint32_t smem_u32(const void* p) {
    uint32_t a;
    asm("{ .reg .u64 t; cvta.to.shared.u64 t, %1; cvt.u32.u64 %0, t; }" : "=r"(a) : "l"(p));
    return a;
}
#define SWZ128(b) ((b) ^ (((b) >> 3) & 0x70))

__device__ __forceinline__ uint4 pack_bf16x8(const float4 a, const float4 b) {
    uint4 r;
    __nv_bfloat162 p;
    p = __floats2bfloat162_rn(a.x, a.y); r.x = *reinterpret_cast<uint32_t*>(&p);
    p = __floats2bfloat162_rn(a.z, a.w); r.y = *reinterpret_cast<uint32_t*>(&p);
    p = __floats2bfloat162_rn(b.x, b.y); r.z = *reinterpret_cast<uint32_t*>(&p);
    p = __floats2bfloat162_rn(b.z, b.w); r.w = *reinterpret_cast<uint32_t*>(&p);
    return r;
}

// ---------------------------------------------------------------------------
// GEMM (+ x->out copy on extra CTAs). fp32 loaded directly, converted to bf16
// in registers, stored to swizzled smem; ldmatrix.trans B path (validated).
// CTA tile M=32 x N=64, BK=64 (16 chunks), 8 warps = 2(m) x 4(n), wtile 16x16.
// Grid: 128 GEMM CTAs + 16 copy CTAs. Epilogue scales by log2(e).
// ---------------------------------------------------------------------------
__global__ __launch_bounds__(256) void gemm_copy_kernel(
    const float* __restrict__ x, const float* __restrict__ T,
    float* __restrict__ out, __half* __restrict__ C)
{
    const int tid = threadIdx.x;
    const int bid = blockIdx.x;

    if (bid >= 128) {
        // ---- x -> out[:, :1024] copy: 16 CTAs x 256 thr x 16 float4 ----
        const int base = (bid - 128) * 4096 + tid;
        #pragma unroll
        for (int r = 0; r < 16; r++) {
            const int idx = base + r * 256;
            const float4 v = reinterpret_cast<const float4*>(x)[idx];
            const int row = idx >> 8;
            const int c4  = idx & 255;
            *reinterpret_cast<float4*>(&out[row * OUTW + c4 * 4]) = v;
        }
        return;
    }

    __shared__ __align__(1024) char sbuf[2][12288];   // [A 4KB | B 8KB] x2

    const int wid = tid >> 5;
    const int lid = tid & 31;
    const int nt = bid & 15;     // 0..15
    const int mt = bid >> 4;     // 0..7
    const int w_m = wid >> 2;    // 0..1
    const int w_n = wid & 3;     // 0..3

    const int ld_row = tid >> 3;           // 0..31
    const int ld_kc  = tid & 7;            // 16B unit
    const uint32_t soff0 = SWZ128((uint32_t)(ld_row * 128 + ld_kc * 16));
    const uint32_t soff1 = SWZ128((uint32_t)((ld_row + 32) * 128 + ld_kc * 16));

    // Global base pointers.
    const float* gA = x + (size_t)(mt * 32 + ld_row) * INF + ld_kc * 8;
    const float* gB = T + (size_t)ld_row * NCOLS + nt * 64 + ld_kc * 8;

    float c[2][4];
    #pragma unroll
    for (int j = 0; j < 2; j++)
        #pragma unroll
        for (int q = 0; q < 4; q++) c[j][q] = 0.0f;

    const int l7  = lid & 7;
    const int lb3 = (lid >> 3) & 1;
    const int lb4 = (lid >> 4) & 1;
    const int a_row_lane = l7 + lb3 * 8;
    const int b_row_lane = l7 + lb3 * 8;
    const int nb = w_n * 16;
    const int mb = w_m * 16;
    const uint32_t b_col_bytes = (uint32_t)(nb + 8 * lb4) * 2;

    const uint32_t sbase0 = smem_u32(sbuf[0]);
    const uint32_t sbase1 = smem_u32(sbuf[1]);

    float4 fA0[2], fB0[4], fA1[2], fB1[4];

    auto load_regs = [&](int ch, float4* fA, float4* fB) {
        const int k0 = ch * 64;
        fA[0] = *reinterpret_cast<const float4*>(gA + k0);
        fA[1] = *reinterpret_cast<const float4*>(gA + k0 + 4);
        const float* gb = gB + (size_t)k0 * NCOLS;
        fB[0] = *reinterpret_cast<const float4*>(gb);
        fB[1] = *reinterpret_cast<const float4*>(gb + 4);
        fB[2] = *reinterpret_cast<const float4*>(gb + 32 * NCOLS);
        fB[3] = *reinterpret_cast<const float4*>(gb + 32 * NCOLS + 4);
    };
    auto sts_stage = [&](int b, const float4* fA, const float4* fB) {
        char* pA = sbuf[b];
        char* pB = sbuf[b] + 4096;
        *reinterpret_cast<uint4*>(pA + soff0) = pack_bf16x8(fA[0], fA[1]);
        *reinterpret_cast<uint4*>(pB + soff0) = pack_bf16x8(fB[0], fB[1]);
        *reinterpret_cast<uint4*>(pB + soff1) = pack_bf16x8(fB[2], fB[3]);
    };
    auto compute = [&](uint32_t sA) {
        const uint32_t sB = sA + 4096;
        #pragma unroll
        for (int s = 0; s < 4; s++) {
            uint32_t b0, b1, b2, b3;
            {
                const uint32_t boff = SWZ128(
                    (uint32_t)((s * 16 + b_row_lane) * 128) + b_col_bytes);
                asm volatile(
                    "ldmatrix.sync.aligned.m8n8.x4.trans.shared.b16 {%0,%1,%2,%3}, [%4];"
                    : "=r"(b0), "=r"(b1), "=r"(b2), "=r"(b3) : "r"(sB + boff));
            }
            uint32_t a0, a1, a2, a3;
            {
                const uint32_t aoff = SWZ128(
                    (uint32_t)((mb + a_row_lane) * 128 + (s * 2 + lb4) * 16));
                asm volatile(
                    "ldmatrix.sync.aligned.m8n8.x4.shared.b16 {%0,%1,%2,%3}, [%4];"
                    : "=r"(a0), "=r"(a1), "=r"(a2), "=r"(a3) : "r"(sA + aoff));
            }
            asm volatile(
                "mma.sync.aligned.m16n8k16.row.col.f32.bf16.bf16.f32 "
                "{%0,%1,%2,%3}, {%4,%5,%6,%7}, {%8,%9}, {%0,%1,%2,%3};"
                : "+f"(c[0][0]), "+f"(c[0][1]), "+f"(c[0][2]), "+f"(c[0][3])
                : "r"(a0), "r"(a1), "r"(a2), "r"(a3), "r"(b0), "r"(b1));
            asm volatile(
                "mma.sync.aligned.m16n8k16.row.col.f32.bf16.bf16.f32 "
                "{%0,%1,%2,%3}, {%4,%5,%6,%7}, {%8,%9}, {%0,%1,%2,%3};"
                : "+f"(c[1][0]), "+f"(c[1][1]), "+f"(c[1][2]), "+f"(c[1][3])
                : "r"(a0), "r"(a1), "r"(a2), "r"(a3), "r"(b2), "r"(b3));
        }
    };

    load_regs(0, fA0, fB0);
    load_regs(1, fA1, fB1);

    #pragma unroll 1
    for (int it = 0; it < 8; it++) {
        const int ch = it * 2;
        sts_stage(0, fA0, fB0);
        if (ch + 2 < 16) load_regs(ch + 2, fA0, fB0);
        __syncthreads();
        compute(sbase0);
        sts_stage(1, fA1, fB1);
        if (ch + 3 < 16) load_regs(ch + 3, fA1, fB1);
        __syncthreads();
        compute(sbase1);
    }

    const float LOG2E = 1.4426950408889634f;
    const int g = lid >> 2;
    const int tig = lid & 3;
    const int row = mt * 32 + mb + g;
    #pragma unroll
    for (int nf = 0; nf < 2; nf++) {
        const int col = nt * 64 + nb + nf * 8 + tig * 2;
        *reinterpret_cast<__half2*>(&C[row * NCOLS + col]) =
            __floats2half2_rn(c[nf][0] * LOG2E, c[nf][1] * LOG2E);
        *reinterpret_cast<__half2*>(&C[(row + 8) * NCOLS + col]) =
            __floats2half2_rn(c[nf][2] * LOG2E, c[nf][3] * LOG2E);
    }
}

// ---------------------------------------------------------------------------
// Pairwise (R14-identical): fp16x2, lanes = two j's, 4 j/iter dual chains,
// ex2.approx.f16x2 on prescaled distances.
// Grid 512 = (o, i-quarter). 512 threads = 64 i-local x 8-way jp-split.
// ---------------------------------------------------------------------------
__global__ __launch_bounds__(512) void pairwise_kernel(
    const __half* __restrict__ Mh, float* __restrict__ out)
{
    const int o  = blockIdx.x >> 2;
    const int iq = blockIdx.x & 3;
    const int il = threadIdx.x & 63;
    const int h  = threadIdx.x >> 6;          // 0..7
    const int i  = iq * 64 + il;
    const int tid = threadIdx.x;

    __shared__ __align__(16) __half2 Msp[128][8];   // [pair][k], lane = j parity
    __shared__ float psum[7][64];

    if (tid < BATCH) {
        const uint4 rv = *reinterpret_cast<const uint4*>(&Mh[tid * NCOLS + o * KD]);
        const __half* hv = reinterpret_cast<const __half*>(&rv);
        const int p = tid >> 1, lane = tid & 1;
        #pragma unroll
        for (int k = 0; k < 8; k++)
            reinterpret_cast<__half*>(&Msp[p][k])[lane] = hv[k];
    }
    __syncthreads();

    __half2 a[8];
    {
        const int p = i >> 1, lane = i & 1;
        #pragma unroll
        for (int k = 0; k < 8; k++)
            a[k] = __half2half2(reinterpret_cast<const __half*>(&Msp[p][k])[lane]);
    }

    __half2 accA = __float2half2_rn(0.0f);
    __half2 accB = __float2half2_rn(0.0f);
    const int jp0 = h * 16;

    #pragma unroll
    for (int it = 0; it < 8; it++) {
        const int jp = jp0 + it * 2;
        const uint4* bpA = reinterpret_cast<const uint4*>(&Msp[jp][0]);
        const uint4* bpB = reinterpret_cast<const uint4*>(&Msp[jp + 1][0]);
        const uint4 uA0 = bpA[0], uA1 = bpA[1];
        const uint4 uB0 = bpB[0], uB1 = bpB[1];
        const __half2* bA = reinterpret_cast<const __half2*>(&uA0);
        const __half2* bA2 = reinterpret_cast<const __half2*>(&uA1);
        const __half2* bB = reinterpret_cast<const __half2*>(&uB0);
        const __half2* bB2 = reinterpret_cast<const __half2*>(&uB1);

        const __half2 tA0 = __hadd2(__habs2(__hsub2(a[0], bA[0])),
                                    __habs2(__hsub2(a[1], bA[1])));
        const __half2 tA1 = __hadd2(__habs2(__hsub2(a[2], bA[2])),
                                    __habs2(__hsub2(a[3], bA[3])));
        const __half2 tA2 = __hadd2(__habs2(__hsub2(a[4], bA2[0])),
                                    __habs2(__hsub2(a[5], bA2[1])));
        const __half2 tA3 = __hadd2(__habs2(__hsub2(a[6], bA2[2])),
                                    __habs2(__hsub2(a[7], bA2[3])));
        const __half2 dA = __hadd2(__hadd2(tA0, tA1), __hadd2(tA2, tA3));
        const __half2 nA = __hneg2(dA);
        __half2 eA;
        asm("ex2.approx.f16x2 %0, %1;"
            : "=r"(*reinterpret_cast<uint32_t*>(&eA))
            : "r"(*reinterpret_cast<const uint32_t*>(&nA)));

        const __half2 tB0 = __hadd2(__habs2(__hsub2(a[0], bB[0])),
                                    __habs2(__hsub2(a[1], bB[1])));
        const __half2 tB1 = __hadd2(__habs2(__hsub2(a[2], bB[2])),
                                    __habs2(__hsub2(a[3], bB[3])));
        const __half2 tB2 = __hadd2(__habs2(__hsub2(a[4], bB2[0])),
                                    __habs2(__hsub2(a[5], bB2[1])));
        const __half2 tB3 = __hadd2(__habs2(__hsub2(a[6], bB2[2])),
                                    __habs2(__hsub2(a[7], bB2[3])));
        const __half2 dB = __hadd2(__hadd2(tB0, tB1), __hadd2(tB2, tB3));
        const __half2 nB = __hneg2(dB);
        __half2 eB;
        asm("ex2.approx.f16x2 %0, %1;"
            : "=r"(*reinterpret_cast<uint32_t*>(&eB))
            : "r"(*reinterpret_cast<const uint32_t*>(&nB)));

        accA = __hadd2(accA, eA);
        accB = __hadd2(accB, eB);
    }

    const __half2 acc = __hadd2(accA, accB);
    const float s = __low2float(acc) + __high2float(acc);

    if (h) psum[h - 1][il] = s;
    __syncthreads();
    if (h == 0) {
        float tot = s - 1.0f;
        #pragma unroll
        for (int q = 0; q < 7; q++) tot += psum[q][il];
        out[i * OUTW + INF + o] = tot;
    }
}

// ---------------------------------------------------------------------------
extern "C" void kernel_launch(void* const* d_in, const int* in_sizes, int n_in,
                              void* d_out, int out_size)
{
    const float* x = (const float*)d_in[0];   // (256, 1024)
    const float* T = (const float*)d_in[1];   // (1024, 1024)
    float* out = (float*)d_out;               // (256, 1152)

    __half* Mh;
    cudaGetSymbolAddress((void**)&Mh, g_Mh);

    gemm_copy_kernel<<<144, 256>>>(x, T, out, Mh);
    pairwise_kernel<<<4 * OUTF, 512>>>(Mh, out);
}

// round 16
// speedup vs baseline: 1.1199x; 1.1199x over previous
#include <cuda_runtime.h>
#include <cuda_bf16.h>
#include <cuda_fp16.h>
#include <cstdint>

#define BATCH 256
#define INF   1024
#define OUTF  128
#define KD    8
#define NCOLS (OUTF * KD)     // 1024
#define OUTW  (INF + OUTF)    // 1152

// Device scratch (no allocs allowed)
__device__ __align__(16) __half g_Mh[BATCH * NCOLS];   // Mh = (x @ T) * log2(e), fp16
__device__ __nv_bfloat16 g_Abf[BATCH * INF];           // x in bf16 (K-major)
__device__ __nv_bfloat16 g_Tbf[INF * NCOLS];           // T in bf16, [k][n] layout

__device__ __forceinline__ uint32_t smem_u32(const void* p) {
    uint32_t a;
    asm("{ .reg .u64 t; cvta.to.shared.u64 t, %1; cvt.u32.u64 %0, t; }" : "=r"(a) : "l"(p));
    return a;
}
#define SWZ128(b) ((b) ^ (((b) >> 3) & 0x70))
#define CP_ASYNC16(saddr, gptr) \
    asm volatile("cp.async.cg.shared.global [%0], [%1], 16;" :: "r"(saddr), "l"(gptr) : "memory")
#define CP_COMMIT() asm volatile("cp.async.commit_group;" ::: "memory")
#define CP_WAIT1()  asm volatile("cp.async.wait_group 1;" ::: "memory")

// ---------------------------------------------------------------------------
// Streaming prep (convert only — x->out copy moved to the pairwise launch):
//   blocks [0,256):   T fp32 -> bf16 (layout unchanged), 4 float4/thread
//   blocks [256,320): x -> bf16, 4 float4/thread
// ---------------------------------------------------------------------------
__global__ __launch_bounds__(256) void prep_kernel(
    const float* __restrict__ x, const float* __restrict__ T,
    __nv_bfloat16* __restrict__ xb, __nv_bfloat16* __restrict__ Tb)
{
    const int tid = threadIdx.x;
    float4 v[4];
    if (blockIdx.x < 256) {
        const int base = blockIdx.x * 1024 + tid;
        #pragma unroll
        for (int r = 0; r < 4; r++)
            v[r] = reinterpret_cast<const float4*>(T)[base + r * 256];
        #pragma unroll
        for (int r = 0; r < 4; r++) {
            const int idx = base + r * 256;
            reinterpret_cast<__nv_bfloat162*>(Tb)[idx * 2] =
                __floats2bfloat162_rn(v[r].x, v[r].y);
            reinterpret_cast<__nv_bfloat162*>(Tb)[idx * 2 + 1] =
                __floats2bfloat162_rn(v[r].z, v[r].w);
        }
    } else {
        const int base = (blockIdx.x - 256) * 1024 + tid;
        #pragma unroll
        for (int r = 0; r < 4; r++)
            v[r] = reinterpret_cast<const float4*>(x)[base + r * 256];
        #pragma unroll
        for (int r = 0; r < 4; r++) {
            const int idx = base + r * 256;
            reinterpret_cast<__nv_bfloat162*>(xb)[idx * 2] =
                __floats2bfloat162_rn(v[r].x, v[r].y);
            reinterpret_cast<__nv_bfloat162*>(xb)[idx * 2 + 1] =
                __floats2bfloat162_rn(v[r].z, v[r].w);
        }
    }
}

// ---------------------------------------------------------------------------
// HMMA GEMM (R13-identical), 3-stage cp.async; B via ldmatrix.trans.
// Epilogue scales by log2(e).
// CTA tile M=32 x N=64, BK=64 (16 chunks). Grid (16 nt, 8 mt) = 128 CTAs.
// ---------------------------------------------------------------------------
#define STAGE_BYTES 12288
#define GEMM_SMEM   (3 * STAGE_BYTES)

__global__ __launch_bounds__(256) void gemm_mma_kernel(
    const __nv_bfloat16* __restrict__ A, const __nv_bfloat16* __restrict__ Tb,
    __half* __restrict__ C)
{
    extern __shared__ __align__(1024) char dsm[];

    const int tid = threadIdx.x;
    const int wid = tid >> 5;
    const int lid = tid & 31;
    const int nt = blockIdx.x;
    const int mt = blockIdx.y;
    const int w_m = wid >> 2;
    const int w_n = wid & 3;

    const uint32_t sbase = smem_u32(dsm);

    const __nv_bfloat16* Ag = A + (size_t)(mt * 32) * INF;
    const __nv_bfloat16* Bg = Tb + nt * 64;

    const int ld_row  = tid >> 3;
    const int ld_kc   = tid & 7;
    const uint32_t soff0 = SWZ128((uint32_t)(ld_row * 128 + ld_kc * 16));
    const uint32_t soff1 = SWZ128((uint32_t)((ld_row + 32) * 128 + ld_kc * 16));

    float c[2][4];
    #pragma unroll
    for (int j = 0; j < 2; j++)
        #pragma unroll
        for (int q = 0; q < 4; q++) c[j][q] = 0.0f;

    const int l7  = lid & 7;
    const int lb3 = (lid >> 3) & 1;
    const int lb4 = (lid >> 4) & 1;
    const int a_row_lane = l7 + lb3 * 8;
    const int b_row_lane = l7 + lb3 * 8;
    const int nb = w_n * 16;
    const int mb = w_m * 16;
    const uint32_t b_col_bytes = (uint32_t)(nb + 8 * lb4) * 2;

    auto load_stage = [&](int st, int k0) {
        const uint32_t sA = sbase + st * STAGE_BYTES;
        const uint32_t sB = sA + 4096;
        const __nv_bfloat16* ga = Ag + ld_row * INF + k0 + ld_kc * 8;
        const __nv_bfloat16* gb = Bg + (size_t)(k0 + ld_row) * NCOLS + ld_kc * 8;
        CP_ASYNC16(sA + soff0, ga);
        CP_ASYNC16(sB + soff0, gb);
        CP_ASYNC16(sB + soff1, gb + 32 * NCOLS);
    };

    load_stage(0, 0);   CP_COMMIT();
    load_stage(1, 64);  CP_COMMIT();

    for (int ch = 0; ch < 16; ch++) {
        CP_WAIT1();
        __syncthreads();
        if (ch + 2 < 16) load_stage((ch + 2) % 3, (ch + 2) * 64);
        CP_COMMIT();

        const uint32_t sA = sbase + (ch % 3) * STAGE_BYTES;
        const uint32_t sB = sA + 4096;

        #pragma unroll
        for (int s = 0; s < 4; s++) {
            uint32_t b0, b1, b2, b3;
            {
                const uint32_t boff = SWZ128(
                    (uint32_t)((s * 16 + b_row_lane) * 128) + b_col_bytes);
                asm volatile(
                    "ldmatrix.sync.aligned.m8n8.x4.trans.shared.b16 {%0,%1,%2,%3}, [%4];"
                    : "=r"(b0), "=r"(b1), "=r"(b2), "=r"(b3) : "r"(sB + boff));
            }
            uint32_t a0, a1, a2, a3;
            {
                const uint32_t aoff = SWZ128(
                    (uint32_t)((mb + a_row_lane) * 128 + (s * 2 + lb4) * 16));
                asm volatile(
                    "ldmatrix.sync.aligned.m8n8.x4.shared.b16 {%0,%1,%2,%3}, [%4];"
                    : "=r"(a0), "=r"(a1), "=r"(a2), "=r"(a3) : "r"(sA + aoff));
            }
            asm volatile(
                "mma.sync.aligned.m16n8k16.row.col.f32.bf16.bf16.f32 "
                "{%0,%1,%2,%3}, {%4,%5,%6,%7}, {%8,%9}, {%0,%1,%2,%3};"
                : "+f"(c[0][0]), "+f"(c[0][1]), "+f"(c[0][2]), "+f"(c[0][3])
                : "r"(a0), "r"(a1), "r"(a2), "r"(a3), "r"(b0), "r"(b1));
            asm volatile(
                "mma.sync.aligned.m16n8k16.row.col.f32.bf16.bf16.f32 "
                "{%0,%1,%2,%3}, {%4,%5,%6,%7}, {%8,%9}, {%0,%1,%2,%3};"
                : "+f"(c[1][0]), "+f"(c[1][1]), "+f"(c[1][2]), "+f"(c[1][3])
                : "r"(a0), "r"(a1), "r"(a2), "r"(a3), "r"(b2), "r"(b3));
        }
    }

    const float LOG2E = 1.4426950408889634f;
    const int g = lid >> 2;
    const int tig = lid & 3;
    const int row = mt * 32 + mb + g;
    #pragma unroll
    for (int nf = 0; nf < 2; nf++) {
        const int col = nt * 64 + nb + nf * 8 + tig * 2;
        *reinterpret_cast<__half2*>(&C[row * NCOLS + col]) =
            __floats2half2_rn(c[nf][0] * LOG2E, c[nf][1] * LOG2E);
        *reinterpret_cast<__half2*>(&C[(row + 8) * NCOLS + col]) =
            __floats2half2_rn(c[nf][2] * LOG2E, c[nf][3] * LOG2E);
    }
}

// ---------------------------------------------------------------------------
// Pairwise (R14 compute) + x->out copy on 16 extra blocks.
// Blocks [0,512): pairwise, grid = (o, i-quarter), 64 i x 8-way jp-split.
// Blocks [512,528): copy x into out[:, :1024], 8 float4/thread.
// ---------------------------------------------------------------------------
__global__ __launch_bounds__(512) void pairwise_kernel(
    const __half* __restrict__ Mh, const float* __restrict__ x,
    float* __restrict__ out)
{
    const int tid = threadIdx.x;

    if (blockIdx.x >= 512) {
        // ---- copy: 16 blocks x 512 thr x 8 float4 = 65536 float4 ----
        const int base = (blockIdx.x - 512) * 4096 + tid;
        float4 v[8];
        #pragma unroll
        for (int r = 0; r < 8; r++)
            v[r] = reinterpret_cast<const float4*>(x)[base + r * 512];
        #pragma unroll
        for (int r = 0; r < 8; r++) {
            const int idx = base + r * 512;
            const int row = idx >> 8;
            const int c4  = idx & 255;
            *reinterpret_cast<float4*>(&out[row * OUTW + c4 * 4]) = v[r];
        }
        return;
    }

    const int o  = blockIdx.x >> 2;
    const int iq = blockIdx.x & 3;
    const int il = tid & 63;
    const int h  = tid >> 6;          // 0..7
    const int i  = iq * 64 + il;

    __shared__ __align__(16) __half2 Msp[128][8];   // [pair][k], lane = j parity
    __shared__ float psum[7][64];

    if (tid < BATCH) {
        const uint4 rv = *reinterpret_cast<const uint4*>(&Mh[tid * NCOLS + o * KD]);
        const __half* hv = reinterpret_cast<const __half*>(&rv);
        const int p = tid >> 1, lane = tid & 1;
        #pragma unroll
        for (int k = 0; k < 8; k++)
            reinterpret_cast<__half*>(&Msp[p][k])[lane] = hv[k];
    }
    __syncthreads();

    __half2 a[8];
    {
        const int p = i >> 1, lane = i & 1;
        #pragma unroll
        for (int k = 0; k < 8; k++)
            a[k] = __half2half2(reinterpret_cast<const __half*>(&Msp[p][k])[lane]);
    }

    __half2 accA = __float2half2_rn(0.0f);
    __half2 accB = __float2half2_rn(0.0f);
    const int jp0 = h * 16;

    #pragma unroll
    for (int it = 0; it < 8; it++) {
        const int jp = jp0 + it * 2;
        const uint4* bpA = reinterpret_cast<const uint4*>(&Msp[jp][0]);
        const uint4* bpB = reinterpret_cast<const uint4*>(&Msp[jp + 1][0]);
        const uint4 uA0 = bpA[0], uA1 = bpA[1];
        const uint4 uB0 = bpB[0], uB1 = bpB[1];
        const __half2* bA = reinterpret_cast<const __half2*>(&uA0);
        const __half2* bA2 = reinterpret_cast<const __half2*>(&uA1);
        const __half2* bB = reinterpret_cast<const __half2*>(&uB0);
        const __half2* bB2 = reinterpret_cast<const __half2*>(&uB1);

        const __half2 tA0 = __hadd2(__habs2(__hsub2(a[0], bA[0])),
                                    __habs2(__hsub2(a[1], bA[1])));
        const __half2 tA1 = __hadd2(__habs2(__hsub2(a[2], bA[2])),
                                    __habs2(__hsub2(a[3], bA[3])));
        const __half2 tA2 = __hadd2(__habs2(__hsub2(a[4], bA2[0])),
                                    __habs2(__hsub2(a[5], bA2[1])));
        const __half2 tA3 = __hadd2(__habs2(__hsub2(a[6], bA2[2])),
                                    __habs2(__hsub2(a[7], bA2[3])));
        const __half2 dA = __hadd2(__hadd2(tA0, tA1), __hadd2(tA2, tA3));
        const __half2 nA = __hneg2(dA);
        __half2 eA;
        asm("ex2.approx.f16x2 %0, %1;"
            : "=r"(*reinterpret_cast<uint32_t*>(&eA))
            : "r"(*reinterpret_cast<const uint32_t*>(&nA)));

        const __half2 tB0 = __hadd2(__habs2(__hsub2(a[0], bB[0])),
                                    __habs2(__hsub2(a[1], bB[1])));
        const __half2 tB1 = __hadd2(__habs2(__hsub2(a[2], bB[2])),
                                    __habs2(__hsub2(a[3], bB[3])));
        const __half2 tB2 = __hadd2(__habs2(__hsub2(a[4], bB2[0])),
                                    __habs2(__hsub2(a[5], bB2[1])));
        const __half2 tB3 = __hadd2(__habs2(__hsub2(a[6], bB2[2])),
                                    __habs2(__hsub2(a[7], bB2[3])));
        const __half2 dB = __hadd2(__hadd2(tB0, tB1), __hadd2(tB2, tB3));
        const __half2 nB = __hneg2(dB);
        __half2 eB;
        asm("ex2.approx.f16x2 %0, %1;"
            : "=r"(*reinterpret_cast<uint32_t*>(&eB))
            : "r"(*reinterpret_cast<const uint32_t*>(&nB)));

        accA = __hadd2(accA, eA);
        accB = __hadd2(accB, eB);
    }

    const __half2 acc = __hadd2(accA, accB);
    const float s = __low2float(acc) + __high2float(acc);

    if (h) psum[h - 1][il] = s;
    __syncthreads();
    if (h == 0) {
        float tot = s - 1.0f;
        #pragma unroll
        for (int q = 0; q < 7; q++) tot += psum[q][il];
        out[i * OUTW + INF + o] = tot;
    }
}

// ---------------------------------------------------------------------------
extern "C" void kernel_launch(void* const* d_in, const int* in_sizes, int n_in,
                              void* d_out, int out_size)
{
    const float* x = (const float*)d_in[0];   // (256, 1024)
    const float* T = (const float*)d_in[1];   // (1024, 1024)
    float* out = (float*)d_out;               // (256, 1152)

    __half* Mh;
    __nv_bfloat16 *Abf, *Tbf;
    cudaGetSymbolAddress((void**)&Mh, g_Mh);
    cudaGetSymbolAddress((void**)&Abf, g_Abf);
    cudaGetSymbolAddress((void**)&Tbf, g_Tbf);

    static bool attr_set = false;
    if (!attr_set) {
        cudaFuncSetAttribute(gemm_mma_kernel,
                             cudaFuncAttributeMaxDynamicSharedMemorySize, GEMM_SMEM);
        attr_set = true;
    }

    prep_kernel<<<320, 256>>>(x, T, Abf, Tbf);

    gemm_mma_kernel<<<dim3(NCOLS / 64, BATCH / 32), 256, GEMM_SMEM>>>(Abf, Tbf, Mh);

    pairwise_kernel<<<512 + 16, 512>>>(Mh, x, out);
}